// round 4
// baseline (speedup 1.0000x reference)
#include <cuda_runtime.h>

#define RAYS 16384
#define SAMP 64
#define NP (RAYS*SAMP)
#define GS 128
#define EE 16
#define HH 64
#define CIN 18

// Scratch (device globals; no allocation allowed)
__device__ float g_rgb[NP*3];
__device__ float g_sigma[NP];

#define FULLMASK 0xffffffffu

// shared-memory float offsets (16B-aligned where float4-loaded)
#define OW1   0
#define OB1   1024
#define OW2   1088
#define OB2   5184
#define OW3   5248
#define OB3   6272
#define OCW1  6288      /* padded 20 floats/row: 64*20 = 1280 */
#define OCB1  7568
#define OCW2  7632
#define OCB2  11728
#define OCW3  11792
#define OCB3  11984
#define SMTOT 11988

__device__ __forceinline__ float softplus100(float z) {
    float a = 100.0f * z;
    float sp = fmaxf(a, 0.0f) + __logf(1.0f + __expf(-fabsf(a)));
    return 0.01f * sp;
}

__device__ __forceinline__ float red4(float z) {
    z += __shfl_xor_sync(FULLMASK, z, 1);
    z += __shfl_xor_sync(FULLMASK, z, 2);
    return z;
}

__global__ void __launch_bounds__(128, 4)
points_kernel(const float* __restrict__ rays_o,
              const float* __restrict__ rays_d,
              const float* __restrict__ grid,
              const float* __restrict__ w1, const float* __restrict__ b1,
              const float* __restrict__ w2, const float* __restrict__ b2,
              const float* __restrict__ w3, const float* __restrict__ b3,
              const float* __restrict__ cw1, const float* __restrict__ cb1,
              const float* __restrict__ cw2, const float* __restrict__ cb2,
              const float* __restrict__ cw3, const float* __restrict__ cb3,
              const float* __restrict__ beta,
              const int* __restrict__ nearp,
              const int* __restrict__ farp,
              float* __restrict__ out)
{
    __shared__ __align__(16) float sm[SMTOT];
    {
        int tid = threadIdx.x;
        for (int t = tid; t < 1024; t += 128) sm[OW1 + t] = w1[t];
        for (int t = tid; t < 64;   t += 128) sm[OB1 + t] = b1[t];
        for (int t = tid; t < 4096; t += 128) sm[OW2 + t] = w2[t];
        for (int t = tid; t < 64;   t += 128) sm[OB2 + t] = b2[t];
        for (int t = tid; t < 1024; t += 128) sm[OW3 + t] = w3[t];
        for (int t = tid; t < 16;   t += 128) sm[OB3 + t] = b3[t];
        for (int t = tid; t < 64*CIN; t += 128) {
            int j = t / CIN, i = t % CIN;
            sm[OCW1 + j*20 + i] = cw1[t];
        }
        for (int t = tid; t < 64;   t += 128) sm[OCB1 + t] = cb1[t];
        for (int t = tid; t < 4096; t += 128) sm[OCW2 + t] = cw2[t];
        for (int t = tid; t < 64;   t += 128) sm[OCB2 + t] = cb2[t];
        for (int t = tid; t < 192;  t += 128) sm[OCW3 + t] = cw3[t];
        for (int t = tid; t < 3;    t += 128) sm[OCB3 + t] = cb3[t];
    }
    __syncthreads();

    int gt = blockIdx.x * 128 + threadIdx.x;    // 4 threads per point
    int p  = gt >> 2;
    int q  = gt & 3;                            // lane-quad id
    int hb = q * 16;                            // owned hidden-unit base
    int r  = p >> 6;
    int s  = p & 63;

    float nearf = (float)nearp[0];
    float farf  = (float)farp[0];
    float dt    = (farf - nearf) * (1.0f / (float)SAMP);
    float tmid  = nearf + ((float)s + 0.5f) * dt;

    // x = rays_o + t_mid * rays_d (no FMA contraction; keep floor() aligned)
    float xc[3];
    #pragma unroll
    for (int c = 0; c < 3; c++) {
        float o = rays_o[3*r + c];
        float d = rays_d[3*r + c];
        xc[c] = __fadd_rn(o, __fmul_rn(tmid, d));
    }

    int   i0[3];
    float f[3];
    bool  inb[3];
    #pragma unroll
    for (int c = 0; c < 3; c++) {
        float graw = __fmul_rn(__fmul_rn(__fadd_rn(__fdiv_rn(xc[c], 1.3f), 1.0f), 0.5f), 127.0f);
        inb[c] = (graw >= 0.0f) && (graw <= 127.0f);
        float gg = fminf(fmaxf(graw, 0.0f), 127.0f);
        int ii = (int)floorf(gg);
        if (ii > 126) ii = 126;
        i0[c] = ii;
        f[c] = gg - (float)ii;
    }
    bool mask = inb[0] && inb[1] && inb[2];

    float wx[2] = {1.0f - f[0], f[0]};
    float wy[2] = {1.0f - f[1], f[1]};
    float wz[2] = {1.0f - f[2], f[2]};
    const int dyq = (q >> 1) & 1;               // this lane's fixed corner (dy,dz)
    const int dzq = q & 1;
    const float wyz = wy[dyq] * wz[dzq];
    int base000 = (i0[0]*GS + i0[1])*GS + i0[2];

    // ---- trilinear gather: 2 corners per lane (dx = 0,1) ----
    float emb[EE];
    #pragma unroll
    for (int i = 0; i < EE; i++) emb[i] = 0.0f;
    #pragma unroll
    for (int dx = 0; dx < 2; dx++) {
        const float w = wx[dx] * wyz;
        const float4* cp = reinterpret_cast<const float4*>(
            grid + (size_t)(base000 + dx*(GS*GS) + dyq*GS + dzq) * EE);
        #pragma unroll
        for (int qq = 0; qq < 4; qq++) {
            float4 v = cp[qq];
            emb[4*qq+0] = fmaf(w, v.x, emb[4*qq+0]);
            emb[4*qq+1] = fmaf(w, v.y, emb[4*qq+1]);
            emb[4*qq+2] = fmaf(w, v.z, emb[4*qq+2]);
            emb[4*qq+3] = fmaf(w, v.w, emb[4*qq+3]);
        }
    }
    #pragma unroll
    for (int i = 0; i < EE; i++) emb[i] = red4(emb[i]);

    // ---- SDF layer1: 16 -> own 16 ----
    float h1o[16];
    #pragma unroll
    for (int jj = 0; jj < 16; jj++) {
        int j = hb + jj;
        float z = sm[OB1 + j];
        const float4* wr = reinterpret_cast<const float4*>(&sm[OW1 + j*EE]);
        #pragma unroll
        for (int qq = 0; qq < 4; qq++) {
            float4 v = wr[qq];
            z = fmaf(emb[4*qq+0], v.x, z);
            z = fmaf(emb[4*qq+1], v.y, z);
            z = fmaf(emb[4*qq+2], v.z, z);
            z = fmaf(emb[4*qq+3], v.w, z);
        }
        h1o[jj] = softplus100(z);
    }

    // ---- SDF layer2: 64 -> own 16 (4 output groups, partial over own 16) ----
    float h2o[16];
    #pragma unroll
    for (int g = 0; g < 4; g++) {
        #pragma unroll
        for (int jj = 0; jj < 16; jj += 2) {
            float z0 = 0.0f, z1 = 0.0f;
            const float4* w0  = reinterpret_cast<const float4*>(&sm[OW2 + (16*g+jj+0)*HH + hb]);
            const float4* w1r = reinterpret_cast<const float4*>(&sm[OW2 + (16*g+jj+1)*HH + hb]);
            #pragma unroll
            for (int k4 = 0; k4 < 4; k4++) {
                float4 a = w0[k4];
                float4 bv = w1r[k4];
                z0 = fmaf(h1o[4*k4+0], a.x, z0);  z1 = fmaf(h1o[4*k4+0], bv.x, z1);
                z0 = fmaf(h1o[4*k4+1], a.y, z0);  z1 = fmaf(h1o[4*k4+1], bv.y, z1);
                z0 = fmaf(h1o[4*k4+2], a.z, z0);  z1 = fmaf(h1o[4*k4+2], bv.z, z1);
                z0 = fmaf(h1o[4*k4+3], a.w, z0);  z1 = fmaf(h1o[4*k4+3], bv.w, z1);
            }
            z0 = red4(z0);
            z1 = red4(z1);
            if (g == q) {
                h2o[jj+0] = softplus100(sm[OB2 + 16*g + jj + 0] + z0);
                h2o[jj+1] = softplus100(sm[OB2 + 16*g + jj + 1] + z1);
            }
        }
    }

    // ---- SDF layer3: own 16 -> 16 outputs (replicated) ----
    float sdf = 0.0f;
    float cin[CIN];
    #pragma unroll
    for (int i = 0; i < EE; i++) {
        float z = 0.0f;
        const float4* wr = reinterpret_cast<const float4*>(&sm[OW3 + i*HH + hb]);
        #pragma unroll
        for (int k4 = 0; k4 < 4; k4++) {
            float4 v = wr[k4];
            z = fmaf(h2o[4*k4+0], v.x, z);
            z = fmaf(h2o[4*k4+1], v.y, z);
            z = fmaf(h2o[4*k4+2], v.z, z);
            z = fmaf(h2o[4*k4+3], v.w, z);
        }
        z = red4(z);
        z += sm[OB3 + i];
        if (i == 0) sdf = z; else cin[i-1] = z;
    }

    // ---- backward (cotangent e0) ----
    #pragma unroll
    for (int kk = 0; kk < 16; kk++) {
        float sig2 = 1.0f - __expf(-100.0f * h2o[kk]);
        h2o[kk] = sm[OW3 + hb + kk] * sig2;       // h2o := dz2 (own 16)
    }
    #pragma unroll
    for (int g = 0; g < 4; g++) {
        float pz[16];
        #pragma unroll
        for (int jj = 0; jj < 16; jj++) pz[jj] = 0.0f;
        #pragma unroll
        for (int kk = 0; kk < 16; kk++) {
            const float4* wr = reinterpret_cast<const float4*>(&sm[OW2 + (hb+kk)*HH + 16*g]);
            float d = h2o[kk];
            #pragma unroll
            for (int j4 = 0; j4 < 4; j4++) {
                float4 v = wr[j4];
                pz[4*j4+0] = fmaf(d, v.x, pz[4*j4+0]);
                pz[4*j4+1] = fmaf(d, v.y, pz[4*j4+1]);
                pz[4*j4+2] = fmaf(d, v.z, pz[4*j4+2]);
                pz[4*j4+3] = fmaf(d, v.w, pz[4*j4+3]);
            }
        }
        #pragma unroll
        for (int jj = 0; jj < 16; jj++) {
            float tot = red4(pz[jj]);
            if (g == q) {
                float sig1 = 1.0f - __expf(-100.0f * h1o[jj]);
                h1o[jj] = tot * sig1;             // h1o := dz1 (own 16)
            }
        }
    }
    float de[EE];
    #pragma unroll
    for (int i = 0; i < EE; i++) de[i] = 0.0f;
    #pragma unroll
    for (int jj = 0; jj < 16; jj++) {
        const float4* wr = reinterpret_cast<const float4*>(&sm[OW1 + (hb+jj)*EE]);
        float d = h1o[jj];
        #pragma unroll
        for (int qq = 0; qq < 4; qq++) {
            float4 v = wr[qq];
            de[4*qq+0] = fmaf(d, v.x, de[4*qq+0]);
            de[4*qq+1] = fmaf(d, v.y, de[4*qq+1]);
            de[4*qq+2] = fmaf(d, v.z, de[4*qq+2]);
            de[4*qq+3] = fmaf(d, v.w, de[4*qq+3]);
        }
    }
    #pragma unroll
    for (int i = 0; i < EE; i++) de[i] = red4(de[i]);

    // ---- trilinear backward: own 2 corners ----
    float gx = 0.0f, gy = 0.0f, gz = 0.0f;
    {
        const float sy = dyq ? 1.0f : -1.0f;
        const float sz = dzq ? 1.0f : -1.0f;
        #pragma unroll
        for (int dx = 0; dx < 2; dx++) {
            const float4* cp = reinterpret_cast<const float4*>(
                grid + (size_t)(base000 + dx*(GS*GS) + dyq*GS + dzq) * EE);
            float dot = 0.0f;
            #pragma unroll
            for (int qq = 0; qq < 4; qq++) {
                float4 v = cp[qq];
                dot = fmaf(de[4*qq+0], v.x, dot);
                dot = fmaf(de[4*qq+1], v.y, dot);
                dot = fmaf(de[4*qq+2], v.z, dot);
                dot = fmaf(de[4*qq+3], v.w, dot);
            }
            float sx = dx ? 1.0f : -1.0f;
            gx = fmaf(sx * wyz,                 dot, gx);
            gy = fmaf(wx[dx] * sy * wz[dzq],    dot, gy);
            gz = fmaf(wx[dx] * wy[dyq] * sz,    dot, gz);
        }
    }
    gx = red4(gx);
    gy = red4(gy);
    gz = red4(gz);

    const float K = 48.846153846153847f;   // 0.5*(G-1)/BOUND
    float dX = gx * (inb[0] ? K : 0.0f);
    float dY = gy * (inb[1] ? K : 0.0f);
    float dZ = gz * (inb[2] ? K : 0.0f);

    if (q == 0) {
        out[RAYS*8 + 3*p + 0] = dX;
        out[RAYS*8 + 3*p + 1] = dY;
        out[RAYS*8 + 3*p + 2] = dZ;
    } else if (q == 1) {
        float be  = 0.015f + fabsf(beta[0]);
        float as  = fabsf(sdf);
        float em1 = __expf(-as / be) - 1.0f;
        float sgn = (sdf > 0.0f) ? 1.0f : ((sdf < 0.0f) ? -1.0f : 0.0f);
        float sg  = (0.5f + 0.5f * sgn * em1) / be;
        g_sigma[p] = mask ? sg : 0.0f;
    }

    float nn  = fmaxf(sqrtf(dX*dX + dY*dY + dZ*dZ), 1e-12f);
    float inv = 1.0f / nn;
    cin[15] = dX * inv;
    cin[16] = dY * inv;
    cin[17] = dZ * inv;

    // ---- color layer1: 18 -> own 16 (ReLU); padded 20-float rows ----
    #pragma unroll
    for (int jj = 0; jj < 16; jj++) {
        int j = hb + jj;
        float z = sm[OCB1 + j];
        const float4* wr = reinterpret_cast<const float4*>(&sm[OCW1 + j*20]);
        #pragma unroll
        for (int qq = 0; qq < 4; qq++) {
            float4 v = wr[qq];
            z = fmaf(cin[4*qq+0], v.x, z);
            z = fmaf(cin[4*qq+1], v.y, z);
            z = fmaf(cin[4*qq+2], v.z, z);
            z = fmaf(cin[4*qq+3], v.w, z);
        }
        const float2 v2 = *reinterpret_cast<const float2*>(&sm[OCW1 + j*20 + 16]);
        z = fmaf(cin[16], v2.x, z);
        z = fmaf(cin[17], v2.y, z);
        h1o[jj] = fmaxf(z, 0.0f);
    }
    // ---- color layer2: 64 -> own 16 (ReLU) ----
    #pragma unroll
    for (int g = 0; g < 4; g++) {
        #pragma unroll
        for (int jj = 0; jj < 16; jj += 2) {
            float z0 = 0.0f, z1 = 0.0f;
            const float4* w0  = reinterpret_cast<const float4*>(&sm[OCW2 + (16*g+jj+0)*HH + hb]);
            const float4* w1r = reinterpret_cast<const float4*>(&sm[OCW2 + (16*g+jj+1)*HH + hb]);
            #pragma unroll
            for (int k4 = 0; k4 < 4; k4++) {
                float4 a = w0[k4];
                float4 bv = w1r[k4];
                z0 = fmaf(h1o[4*k4+0], a.x, z0);  z1 = fmaf(h1o[4*k4+0], bv.x, z1);
                z0 = fmaf(h1o[4*k4+1], a.y, z0);  z1 = fmaf(h1o[4*k4+1], bv.y, z1);
                z0 = fmaf(h1o[4*k4+2], a.z, z0);  z1 = fmaf(h1o[4*k4+2], bv.z, z1);
                z0 = fmaf(h1o[4*k4+3], a.w, z0);  z1 = fmaf(h1o[4*k4+3], bv.w, z1);
            }
            z0 = red4(z0);
            z1 = red4(z1);
            if (g == q) {
                h2o[jj+0] = fmaxf(sm[OCB2 + 16*g + jj + 0] + z0, 0.0f);
                h2o[jj+1] = fmaxf(sm[OCB2 + 16*g + jj + 1] + z1, 0.0f);
            }
        }
    }
    // ---- color layer3: own 16 -> 3 (sigmoid) ----
    #pragma unroll
    for (int i = 0; i < 3; i++) {
        float z = 0.0f;
        const float4* wr = reinterpret_cast<const float4*>(&sm[OCW3 + i*HH + hb]);
        #pragma unroll
        for (int k4 = 0; k4 < 4; k4++) {
            float4 v = wr[k4];
            z = fmaf(h2o[4*k4+0], v.x, z);
            z = fmaf(h2o[4*k4+1], v.y, z);
            z = fmaf(h2o[4*k4+2], v.z, z);
            z = fmaf(h2o[4*k4+3], v.w, z);
        }
        z = red4(z);
        z += sm[OCB3 + i];
        if (q == 0) g_rgb[3*p + i] = 1.0f / (1.0f + __expf(-z));
    }
}

__global__ void __launch_bounds__(128)
render_kernel(const float* __restrict__ rays_d_norm,
              const int* __restrict__ nearp, const int* __restrict__ farp,
              float* __restrict__ out)
{
    int r = blockIdx.x * 128 + threadIdx.x;
    if (r >= RAYS) return;
    float nearf = (float)nearp[0];
    float farf  = (float)farp[0];
    float dt    = (farf - nearf) * (1.0f / (float)SAMP);
    const float* grads = out + RAYS*8;

    float cs = 0.0f;
    float aR = 0.f, aG = 0.f, aB = 0.f, aD = 0.f;
    float aN0 = 0.f, aN1 = 0.f, aN2 = 0.f, aA = 0.f;
    for (int s = 0; s < SAMP; s++) {
        int p = r * SAMP + s;
        float dd = g_sigma[p] * dt;
        float T  = __expf(-cs);          // exclusive prefix
        cs += dd;
        float w = (1.0f - __expf(-dd)) * T;
        aR = fmaf(w, g_rgb[3*p + 0], aR);
        aG = fmaf(w, g_rgb[3*p + 1], aG);
        aB = fmaf(w, g_rgb[3*p + 2], aB);
        float tm = nearf + ((float)s + 0.5f) * dt;
        aD = fmaf(w, tm, aD);
        float gx = grads[3*p + 0], gy = grads[3*p + 1], gz = grads[3*p + 2];
        float nn = fmaxf(sqrtf(gx*gx + gy*gy + gz*gz), 1e-12f);
        float wi = w / nn;
        aN0 = fmaf(wi, gx, aN0);
        aN1 = fmaf(wi, gy, aN1);
        aN2 = fmaf(wi, gz, aN2);
        aA += w;
    }
    float ir = 1.0f / rays_d_norm[r];
    out[8*r + 0] = aR;
    out[8*r + 1] = aG;
    out[8*r + 2] = aB;
    out[8*r + 3] = aD * ir;
    out[8*r + 4] = aN0;
    out[8*r + 5] = aN1;
    out[8*r + 6] = aN2;
    out[8*r + 7] = aA;
}

extern "C" void kernel_launch(void* const* d_in, const int* in_sizes, int n_in,
                              void* d_out, int out_size)
{
    const float* rays_o      = (const float*)d_in[0];
    const float* rays_d      = (const float*)d_in[1];
    const float* rays_d_norm = (const float*)d_in[2];
    const float* grid        = (const float*)d_in[3];
    const float* sw1 = (const float*)d_in[4];
    const float* sb1 = (const float*)d_in[5];
    const float* sw2 = (const float*)d_in[6];
    const float* sb2 = (const float*)d_in[7];
    const float* sw3 = (const float*)d_in[8];
    const float* sb3 = (const float*)d_in[9];
    const float* cw1 = (const float*)d_in[10];
    const float* cb1 = (const float*)d_in[11];
    const float* cw2 = (const float*)d_in[12];
    const float* cb2 = (const float*)d_in[13];
    const float* cw3 = (const float*)d_in[14];
    const float* cb3 = (const float*)d_in[15];
    const float* beta  = (const float*)d_in[16];
    const int*   nearp = (const int*)d_in[17];
    const int*   farp  = (const int*)d_in[18];
    float* out = (float*)d_out;

    points_kernel<<<(NP*4)/128, 128>>>(rays_o, rays_d, grid,
                                       sw1, sb1, sw2, sb2, sw3, sb3,
                                       cw1, cb1, cw2, cb2, cw3, cb3,
                                       beta, nearp, farp, out);
    render_kernel<<<RAYS/128, 128>>>(rays_d_norm, nearp, farp, out);
}

// round 6
// speedup vs baseline: 5.1893x; 5.1893x over previous
#include <cuda_runtime.h>

#define RAYS 16384
#define SAMP 64
#define NP (RAYS*SAMP)
#define GS 128
#define EE 16
#define HH 64
#define CIN 18
#define BP 128            // points per block
#define NT 128            // threads per block

// Scratch (device globals; no allocation allowed)
__device__ float g_rgb[NP*3];
__device__ float g_sigma[NP];

// ---- dynamic smem float offsets (all float4-aligned where needed) ----
#define OFF_W1T   0        // [16][64]  W1t[i][j] = w1[j*16+i]
#define OFF_W1    1024     // [64][16]  w1 row-major
#define OFF_W3T   2048     // [64][16]  W3t[k][i] = w3[i*64+k]
#define OFF_B1    3072     // 64
#define OFF_B2    3136     // 64
#define OFF_B3    3200     // 16
#define OFF_CB1   3216     // 64
#define OFF_CB2   3280     // 64
#define OFF_CB3   3344     // 4
#define OFF_CW3T  3348     // [64][4]   CW3t[k][i] = cw3[i*64+k]
#define OFF_WBIG  3604     // [64][64]  Wt2 -> W2 -> CW1t -> CWt2
#define OFF_F     7700     // [18][128] emb/feat+normals
#define OFF_HA    10004    // [64][128]
#define OFF_HB    18196    // [64][128] (also 64x65 stage area)
#define SM_FLOATS 26388
#define SM_BYTES  (SM_FLOATS*4)

extern __shared__ float sm[];

__device__ __forceinline__ float softplus100(float z) {
    float a = 100.0f * z;
    float sp = fmaxf(a, 0.0f) + __logf(1.0f + __expf(-fabsf(a)));
    return 0.01f * sp;
}

// MODE 0: softplus100(acc + bias); MODE 1: relu(acc + bias);
// MODE 2: dz1 = acc * (1 - exp(-100 * h_prev)) with h_prev read from Hout.
template<int K, int MODE>
__device__ __forceinline__ void gemm128(const float* __restrict__ Wt,
                                        const float* __restrict__ Hin,
                                        float* __restrict__ Hout,
                                        const float* __restrict__ bias,
                                        int tt)
{
    const int pt0 = (tt & 15) * 8;
    const int u0  = (tt >> 4) * 8;
    float acc[8][8];
    #pragma unroll
    for (int i = 0; i < 8; i++)
        #pragma unroll
        for (int j = 0; j < 8; j++) acc[i][j] = 0.0f;

    #pragma unroll 8
    for (int k = 0; k < K; k++) {
        float4 a0 = *(const float4*)&Hin[k*BP + pt0];
        float4 a1 = *(const float4*)&Hin[k*BP + pt0 + 4];
        float4 w0 = *(const float4*)&Wt[k*64 + u0];
        float4 w1v = *(const float4*)&Wt[k*64 + u0 + 4];
        float a[8] = {a0.x,a0.y,a0.z,a0.w,a1.x,a1.y,a1.z,a1.w};
        float w[8] = {w0.x,w0.y,w0.z,w0.w,w1v.x,w1v.y,w1v.z,w1v.w};
        #pragma unroll
        for (int i = 0; i < 8; i++)
            #pragma unroll
            for (int j = 0; j < 8; j++)
                acc[i][j] = fmaf(a[i], w[j], acc[i][j]);
    }

    #pragma unroll
    for (int j = 0; j < 8; j++) {
        const int u = u0 + j;
        float* orow = &Hout[u*BP + pt0];
        float vin[8];
        if (MODE == 2) {
            float4 p0 = *(const float4*)&orow[0];
            float4 p1 = *(const float4*)&orow[4];
            vin[0]=p0.x; vin[1]=p0.y; vin[2]=p0.z; vin[3]=p0.w;
            vin[4]=p1.x; vin[5]=p1.y; vin[6]=p1.z; vin[7]=p1.w;
        }
        float res[8];
        float bj = (MODE == 2) ? 0.0f : bias[u];
        #pragma unroll
        for (int i = 0; i < 8; i++) {
            float z = acc[i][j];
            if (MODE == 0)      res[i] = softplus100(z + bj);
            else if (MODE == 1) res[i] = fmaxf(z + bj, 0.0f);
            else                res[i] = z * (1.0f - __expf(-100.0f * vin[i]));
        }
        *(float4*)&orow[0] = make_float4(res[0], res[1], res[2], res[3]);
        *(float4*)&orow[4] = make_float4(res[4], res[5], res[6], res[7]);
    }
}

__global__ void __launch_bounds__(NT)
points_kernel(const float* __restrict__ rays_o,
              const float* __restrict__ rays_d,
              const float* __restrict__ grid,
              const float* __restrict__ w1, const float* __restrict__ b1,
              const float* __restrict__ w2, const float* __restrict__ b2,
              const float* __restrict__ w3, const float* __restrict__ b3,
              const float* __restrict__ cw1, const float* __restrict__ cb1,
              const float* __restrict__ cw2, const float* __restrict__ cb2,
              const float* __restrict__ cw3, const float* __restrict__ cb3,
              const float* __restrict__ beta,
              const int* __restrict__ nearp,
              const int* __restrict__ farp,
              float* __restrict__ out)
{
    const int tt = threadIdx.x;
    const int p  = blockIdx.x * BP + tt;
    const int r  = p >> 6;
    const int s  = p & 63;

    // ---------- phase 0a: weight loads + stage + gather ----------
    for (int t = tt; t < 1024; t += NT) { int i = t >> 6, j = t & 63; sm[OFF_W1T + t] = w1[j*16 + i]; }
    for (int t = tt; t < 1024; t += NT) sm[OFF_W1 + t] = w1[t];
    for (int t = tt; t < 1024; t += NT) { int k = t >> 4, i = t & 15; sm[OFF_W3T + t] = w3[i*64 + k]; }
    for (int t = tt; t < 64; t += NT) {
        sm[OFF_B1 + t] = b1[t]; sm[OFF_B2 + t] = b2[t];
        sm[OFF_CB1 + t] = cb1[t]; sm[OFF_CB2 + t] = cb2[t];
    }
    if (tt < 16) sm[OFF_B3 + tt] = b3[tt];
    if (tt < 4)  sm[OFF_CB3 + tt] = (tt < 3) ? cb3[tt] : 0.0f;
    for (int t = tt; t < 256; t += NT) { int k = t >> 2, i = t & 3; sm[OFF_CW3T + t] = (i < 3) ? cw3[i*64 + k] : 0.0f; }
    // stage w2 coalesced with pitch 65 (for transpose into Wt2)
    for (int t = tt; t < 4096; t += NT) { int j = t >> 6, k = t & 63; sm[OFF_HB + j*65 + k] = w2[t]; }

    // ---- per-point setup + trilinear gather (all 8 corners, this thread) ----
    float nearf = (float)nearp[0];
    float farf  = (float)farp[0];
    float dt    = (farf - nearf) * (1.0f / (float)SAMP);
    float tmid  = nearf + ((float)s + 0.5f) * dt;

    float f[3]; int i0[3]; bool inb[3];
    #pragma unroll
    for (int c = 0; c < 3; c++) {
        float o = rays_o[3*r + c];
        float d = rays_d[3*r + c];
        float xcc = __fadd_rn(o, __fmul_rn(tmid, d));
        float graw = __fmul_rn(__fmul_rn(__fadd_rn(__fdiv_rn(xcc, 1.3f), 1.0f), 0.5f), 127.0f);
        inb[c] = (graw >= 0.0f) && (graw <= 127.0f);
        float gg = fminf(fmaxf(graw, 0.0f), 127.0f);
        int ii = (int)floorf(gg);
        if (ii > 126) ii = 126;
        i0[c] = ii;
        f[c] = gg - (float)ii;
    }
    const bool mask = inb[0] && inb[1] && inb[2];
    const int base000 = (i0[0]*GS + i0[1])*GS + i0[2];

    {
        float wx[2] = {1.0f - f[0], f[0]};
        float wy[2] = {1.0f - f[1], f[1]};
        float wz[2] = {1.0f - f[2], f[2]};
        float emb[EE];
        #pragma unroll
        for (int i = 0; i < EE; i++) emb[i] = 0.0f;
        #pragma unroll
        for (int c = 0; c < 8; c++) {
            const int dx = (c >> 2) & 1, dy = (c >> 1) & 1, dz = c & 1;
            const float w = wx[dx] * wy[dy] * wz[dz];
            const float4* cp = reinterpret_cast<const float4*>(
                grid + (size_t)(base000 + dx*(GS*GS) + dy*GS + dz) * EE);
            #pragma unroll
            for (int q = 0; q < 4; q++) {
                float4 v = cp[q];
                emb[4*q+0] = fmaf(w, v.x, emb[4*q+0]);
                emb[4*q+1] = fmaf(w, v.y, emb[4*q+1]);
                emb[4*q+2] = fmaf(w, v.z, emb[4*q+2]);
                emb[4*q+3] = fmaf(w, v.w, emb[4*q+3]);
            }
        }
        #pragma unroll
        for (int i = 0; i < EE; i++) sm[OFF_F + i*BP + tt] = emb[i];
    }
    __syncthreads();

    // ---------- phase 0b: transpose Wt2 + L1 fwd GEMM ----------
    for (int t = tt; t < 4096; t += NT) { int k = t >> 6, j = t & 63; sm[OFF_WBIG + k*64 + j] = sm[OFF_HB + j*65 + k]; }
    gemm128<16, 0>(sm + OFF_W1T, sm + OFF_F, sm + OFF_HA, sm + OFF_B1, tt);
    __syncthreads();

    // ---------- phase 2: L2 fwd GEMM ----------
    gemm128<64, 0>(sm + OFF_WBIG, sm + OFF_HA, sm + OFF_HB, sm + OFF_B2, tt);
    __syncthreads();

    // ---------- phase 3: load W2 (bwd layout) + L3 fwd (scalar) + dz2 + sigma ----------
    for (int t = tt; t < 4096; t += NT) sm[OFF_WBIG + t] = w2[t];
    {
        float o[16];
        #pragma unroll
        for (int i = 0; i < 16; i++) o[i] = 0.0f;
        #pragma unroll 8
        for (int k = 0; k < 64; k++) {
            float h2k = sm[OFF_HB + k*BP + tt];
            const float4* wr = reinterpret_cast<const float4*>(&sm[OFF_W3T + k*16]);
            #pragma unroll
            for (int q = 0; q < 4; q++) {
                float4 v = wr[q];
                o[4*q+0] = fmaf(h2k, v.x, o[4*q+0]);
                o[4*q+1] = fmaf(h2k, v.y, o[4*q+1]);
                o[4*q+2] = fmaf(h2k, v.z, o[4*q+2]);
                o[4*q+3] = fmaf(h2k, v.w, o[4*q+3]);
            }
            // dz2 overwrite (same column owned by this thread)
            float dz2 = sm[OFF_W3T + k*16 + 0] * (1.0f - __expf(-100.0f * h2k));
            sm[OFF_HB + k*BP + tt] = dz2;
        }
        float sdf = o[0] + sm[OFF_B3 + 0];
        #pragma unroll
        for (int i = 1; i < 16; i++) sm[OFF_F + (i-1)*BP + tt] = o[i] + sm[OFF_B3 + i];
        // Laplace-CDF sigma
        float be  = 0.015f + fabsf(beta[0]);
        float as  = fabsf(sdf);
        float em1 = __expf(-as / be) - 1.0f;
        float sgn = (sdf > 0.0f) ? 1.0f : ((sdf < 0.0f) ? -1.0f : 0.0f);
        float sg  = (0.5f + 0.5f * sgn * em1) / be;
        g_sigma[p] = mask ? sg : 0.0f;
    }
    __syncthreads();

    // ---------- phase 4: L2 bwd GEMM (dz1 into HA, using sigma' from h1) ----------
    gemm128<64, 2>(sm + OFF_WBIG, sm + OFF_HB, sm + OFF_HA, sm + OFF_B1, tt);
    __syncthreads();

    // ---------- phase 5: load CW1t + stage cw2 + d_emb + trilinear bwd ----------
    for (int t = tt; t < 18*64; t += NT) { int i = t >> 6, j = t & 63; sm[OFF_WBIG + t] = cw1[j*CIN + i]; }
    for (int t = tt; t < 4096; t += NT) { int j = t >> 6, k = t & 63; sm[OFF_HB + j*65 + k] = cw2[t]; }
    {
        float o[16];
        #pragma unroll
        for (int i = 0; i < 16; i++) o[i] = 0.0f;
        #pragma unroll 8
        for (int j = 0; j < 64; j++) {
            float d = sm[OFF_HA + j*BP + tt];
            const float4* wr = reinterpret_cast<const float4*>(&sm[OFF_W1 + j*16]);
            #pragma unroll
            for (int q = 0; q < 4; q++) {
                float4 v = wr[q];
                o[4*q+0] = fmaf(d, v.x, o[4*q+0]);
                o[4*q+1] = fmaf(d, v.y, o[4*q+1]);
                o[4*q+2] = fmaf(d, v.z, o[4*q+2]);
                o[4*q+3] = fmaf(d, v.w, o[4*q+3]);
            }
        }
        // trilinear backward: re-gather corners, dot with o (=d_emb)
        float wx[2] = {1.0f - f[0], f[0]};
        float wy[2] = {1.0f - f[1], f[1]};
        float wz[2] = {1.0f - f[2], f[2]};
        float gx = 0.0f, gy = 0.0f, gz = 0.0f;
        #pragma unroll
        for (int c = 0; c < 8; c++) {
            const int dx = (c >> 2) & 1, dy = (c >> 1) & 1, dz = c & 1;
            const float4* cp = reinterpret_cast<const float4*>(
                grid + (size_t)(base000 + dx*(GS*GS) + dy*GS + dz) * EE);
            float dot = 0.0f;
            #pragma unroll
            for (int q = 0; q < 4; q++) {
                float4 v = cp[q];
                dot = fmaf(o[4*q+0], v.x, dot);
                dot = fmaf(o[4*q+1], v.y, dot);
                dot = fmaf(o[4*q+2], v.z, dot);
                dot = fmaf(o[4*q+3], v.w, dot);
            }
            float sx = dx ? 1.0f : -1.0f;
            float sy = dy ? 1.0f : -1.0f;
            float sz = dz ? 1.0f : -1.0f;
            gx = fmaf(sx * wy[dy] * wz[dz], dot, gx);
            gy = fmaf(wx[dx] * sy * wz[dz], dot, gy);
            gz = fmaf(wx[dx] * wy[dy] * sz, dot, gz);
        }
        const float K = 48.846153846153847f;   // 0.5*(G-1)/BOUND
        float dX = gx * (inb[0] ? K : 0.0f);
        float dY = gy * (inb[1] ? K : 0.0f);
        float dZ = gz * (inb[2] ? K : 0.0f);
        out[RAYS*8 + 3*p + 0] = dX;
        out[RAYS*8 + 3*p + 1] = dY;
        out[RAYS*8 + 3*p + 2] = dZ;
        float nn  = fmaxf(sqrtf(dX*dX + dY*dY + dZ*dZ), 1e-12f);
        float inv = 1.0f / nn;
        sm[OFF_F + 15*BP + tt] = dX * inv;
        sm[OFF_F + 16*BP + tt] = dY * inv;
        sm[OFF_F + 17*BP + tt] = dZ * inv;
    }
    __syncthreads();

    // ---------- phase 6: color L1 GEMM ----------
    gemm128<18, 1>(sm + OFF_WBIG, sm + OFF_F, sm + OFF_HA, sm + OFF_CB1, tt);
    __syncthreads();

    // ---------- phase 7: transpose CWt2 ----------
    for (int t = tt; t < 4096; t += NT) { int k = t >> 6, j = t & 63; sm[OFF_WBIG + k*64 + j] = sm[OFF_HB + j*65 + k]; }
    __syncthreads();

    // ---------- phase 8: color L2 GEMM ----------
    gemm128<64, 1>(sm + OFF_WBIG, sm + OFF_HA, sm + OFF_HB, sm + OFF_CB2, tt);
    __syncthreads();

    // ---------- phase 9: color L3 (scalar) ----------
    {
        float a0 = 0.0f, a1 = 0.0f, a2 = 0.0f;
        #pragma unroll 8
        for (int k = 0; k < 64; k++) {
            float hk = sm[OFF_HB + k*BP + tt];
            float4 cw = *(const float4*)&sm[OFF_CW3T + k*4];
            a0 = fmaf(hk, cw.x, a0);
            a1 = fmaf(hk, cw.y, a1);
            a2 = fmaf(hk, cw.z, a2);
        }
        a0 += sm[OFF_CB3 + 0];
        a1 += sm[OFF_CB3 + 1];
        a2 += sm[OFF_CB3 + 2];
        g_rgb[3*p + 0] = 1.0f / (1.0f + __expf(-a0));
        g_rgb[3*p + 1] = 1.0f / (1.0f + __expf(-a1));
        g_rgb[3*p + 2] = 1.0f / (1.0f + __expf(-a2));
    }
}

__global__ void __launch_bounds__(128)
render_kernel(const float* __restrict__ rays_d_norm,
              const int* __restrict__ nearp, const int* __restrict__ farp,
              float* __restrict__ out)
{
    int r = blockIdx.x * 128 + threadIdx.x;
    if (r >= RAYS) return;
    float nearf = (float)nearp[0];
    float farf  = (float)farp[0];
    float dt    = (farf - nearf) * (1.0f / (float)SAMP);
    const float* grads = out + RAYS*8;

    float cs = 0.0f;
    float aR = 0.f, aG = 0.f, aB = 0.f, aD = 0.f;
    float aN0 = 0.f, aN1 = 0.f, aN2 = 0.f, aA = 0.f;
    for (int s = 0; s < SAMP; s++) {
        int p = r * SAMP + s;
        float dd = g_sigma[p] * dt;
        float T  = __expf(-cs);          // exclusive prefix
        cs += dd;
        float w = (1.0f - __expf(-dd)) * T;
        aR = fmaf(w, g_rgb[3*p + 0], aR);
        aG = fmaf(w, g_rgb[3*p + 1], aG);
        aB = fmaf(w, g_rgb[3*p + 2], aB);
        float tm = nearf + ((float)s + 0.5f) * dt;
        aD = fmaf(w, tm, aD);
        float gx = grads[3*p + 0], gy = grads[3*p + 1], gz = grads[3*p + 2];
        float nn = fmaxf(sqrtf(gx*gx + gy*gy + gz*gz), 1e-12f);
        float wi = w / nn;
        aN0 = fmaf(wi, gx, aN0);
        aN1 = fmaf(wi, gy, aN1);
        aN2 = fmaf(wi, gz, aN2);
        aA += w;
    }
    float ir = 1.0f / rays_d_norm[r];
    out[8*r + 0] = aR;
    out[8*r + 1] = aG;
    out[8*r + 2] = aB;
    out[8*r + 3] = aD * ir;
    out[8*r + 4] = aN0;
    out[8*r + 5] = aN1;
    out[8*r + 6] = aN2;
    out[8*r + 7] = aA;
}

extern "C" void kernel_launch(void* const* d_in, const int* in_sizes, int n_in,
                              void* d_out, int out_size)
{
    const float* rays_o      = (const float*)d_in[0];
    const float* rays_d      = (const float*)d_in[1];
    const float* rays_d_norm = (const float*)d_in[2];
    const float* grid        = (const float*)d_in[3];
    const float* sw1 = (const float*)d_in[4];
    const float* sb1 = (const float*)d_in[5];
    const float* sw2 = (const float*)d_in[6];
    const float* sb2 = (const float*)d_in[7];
    const float* sw3 = (const float*)d_in[8];
    const float* sb3 = (const float*)d_in[9];
    const float* cw1 = (const float*)d_in[10];
    const float* cb1 = (const float*)d_in[11];
    const float* cw2 = (const float*)d_in[12];
    const float* cb2 = (const float*)d_in[13];
    const float* cw3 = (const float*)d_in[14];
    const float* cb3 = (const float*)d_in[15];
    const float* beta  = (const float*)d_in[16];
    const int*   nearp = (const int*)d_in[17];
    const int*   farp  = (const int*)d_in[18];
    float* out = (float*)d_out;

    cudaFuncSetAttribute(points_kernel,
                         cudaFuncAttributeMaxDynamicSharedMemorySize, SM_BYTES);

    points_kernel<<<NP/BP, NT, SM_BYTES>>>(rays_o, rays_d, grid,
                                           sw1, sb1, sw2, sb2, sw3, sb3,
                                           cw1, cb1, cw2, cb2, cw3, cb3,
                                           beta, nearp, farp, out);
    render_kernel<<<RAYS/128, 128>>>(rays_d_norm, nearp, farp, out);
}

// round 7
// speedup vs baseline: 5.6545x; 1.0896x over previous
#include <cuda_runtime.h>

#define RAYS 16384
#define SAMP 64
#define NP (RAYS*SAMP)
#define GS 128
#define EE 16
#define HH 64
#define CIN 18
#define BP 128            // points per block
#define NT 128            // threads per block

// Scratch (device globals; no allocation allowed)
__device__ float g_rgb[NP*3];
__device__ float g_sigma[NP];

// ---- dynamic smem float offsets (all float4-aligned where needed) ----
#define OFF_W1T   0        // [16][64]  W1t[i][j] = w1[j*16+i]
#define OFF_W1    1024     // [64][16]  w1 row-major
#define OFF_W3T   2048     // [64][16]  W3t[k][i] = w3[i*64+k]
#define OFF_B1    3072     // 64
#define OFF_B2    3136     // 64
#define OFF_B3    3200     // 16
#define OFF_CB1   3216     // 64
#define OFF_CB2   3280     // 64
#define OFF_CB3   3344     // 4
#define OFF_CW3T  3348     // [64][4]   CW3t[k][i] = cw3[i*64+k]
#define OFF_WBIG  3604     // [64][64]  Wt2 -> W2 -> CW1t -> CWt2
#define OFF_F     7700     // [18][128] emb/feat+normals
#define OFF_HA    10004    // [64][128]
#define OFF_HB    18196    // [64][128] (also 64x65 stage area)
#define SM_FLOATS 26388
#define SM_BYTES  (SM_FLOATS*4)

extern __shared__ float sm[];

typedef unsigned long long u64;

__device__ __forceinline__ u64 pack2(float x, float y) {
    u64 d;
    asm("mov.b64 %0, {%1, %2};" : "=l"(d) : "f"(x), "f"(y));
    return d;
}
__device__ __forceinline__ u64 fma2(u64 a, u64 b, u64 c) {
    u64 d;
    asm("fma.rn.f32x2 %0, %1, %2, %3;" : "=l"(d) : "l"(a), "l"(b), "l"(c));
    return d;
}
__device__ __forceinline__ float2 unpack2(u64 v) {
    float2 r;
    asm("mov.b64 {%0, %1}, %2;" : "=f"(r.x), "=f"(r.y) : "l"(v));
    return r;
}

__device__ __forceinline__ float softplus100(float z) {
    float a = 100.0f * z;
    float sp = fmaxf(a, 0.0f) + __logf(1.0f + __expf(-fabsf(a)));
    return 0.01f * sp;
}

// MODE 0: softplus100(acc + bias); MODE 1: relu(acc + bias);
// MODE 2: dz1 = acc * (1 - exp(-100 * h_prev)) with h_prev read from Hout.
// Packed f32x2 inner loop: two adjacent points share one weight broadcast.
template<int K, int MODE>
__device__ __forceinline__ void gemm128(const float* __restrict__ Wt,
                                        const float* __restrict__ Hin,
                                        float* __restrict__ Hout,
                                        const float* __restrict__ bias,
                                        int tt)
{
    const int pt0 = (tt & 15) * 8;
    const int u0  = (tt >> 4) * 8;
    u64 acc[4][8];
    #pragma unroll
    for (int i = 0; i < 4; i++)
        #pragma unroll
        for (int j = 0; j < 8; j++) acc[i][j] = 0ull;

    #pragma unroll 8
    for (int k = 0; k < K; k++) {
        const ulonglong2* ap = (const ulonglong2*)&Hin[k*BP + pt0];
        ulonglong2 A0 = ap[0], A1 = ap[1];
        u64 a[4] = {A0.x, A0.y, A1.x, A1.y};
        float4 w0  = *(const float4*)&Wt[k*64 + u0];
        float4 w1v = *(const float4*)&Wt[k*64 + u0 + 4];
        u64 bw[8] = {pack2(w0.x,w0.x),  pack2(w0.y,w0.y),  pack2(w0.z,w0.z),  pack2(w0.w,w0.w),
                     pack2(w1v.x,w1v.x), pack2(w1v.y,w1v.y), pack2(w1v.z,w1v.z), pack2(w1v.w,w1v.w)};
        #pragma unroll
        for (int i = 0; i < 4; i++)
            #pragma unroll
            for (int j = 0; j < 8; j++)
                acc[i][j] = fma2(a[i], bw[j], acc[i][j]);
    }

    #pragma unroll
    for (int j = 0; j < 8; j++) {
        const int u = u0 + j;
        float* orow = &Hout[u*BP + pt0];
        float vin[8];
        if (MODE == 2) {
            float4 p0 = *(const float4*)&orow[0];
            float4 p1 = *(const float4*)&orow[4];
            vin[0]=p0.x; vin[1]=p0.y; vin[2]=p0.z; vin[3]=p0.w;
            vin[4]=p1.x; vin[5]=p1.y; vin[6]=p1.z; vin[7]=p1.w;
        }
        float accs[8];
        #pragma unroll
        for (int i2 = 0; i2 < 4; i2++) {
            float2 v = unpack2(acc[i2][j]);
            accs[2*i2+0] = v.x;
            accs[2*i2+1] = v.y;
        }
        float res[8];
        float bj = (MODE == 2) ? 0.0f : bias[u];
        #pragma unroll
        for (int i = 0; i < 8; i++) {
            float z = accs[i];
            if (MODE == 0)      res[i] = softplus100(z + bj);
            else if (MODE == 1) res[i] = fmaxf(z + bj, 0.0f);
            else                res[i] = z * (1.0f - __expf(-100.0f * vin[i]));
        }
        *(float4*)&orow[0] = make_float4(res[0], res[1], res[2], res[3]);
        *(float4*)&orow[4] = make_float4(res[4], res[5], res[6], res[7]);
    }
}

__global__ void __launch_bounds__(NT)
points_kernel(const float* __restrict__ rays_o,
              const float* __restrict__ rays_d,
              const float* __restrict__ grid,
              const float* __restrict__ w1, const float* __restrict__ b1,
              const float* __restrict__ w2, const float* __restrict__ b2,
              const float* __restrict__ w3, const float* __restrict__ b3,
              const float* __restrict__ cw1, const float* __restrict__ cb1,
              const float* __restrict__ cw2, const float* __restrict__ cb2,
              const float* __restrict__ cw3, const float* __restrict__ cb3,
              const float* __restrict__ beta,
              const int* __restrict__ nearp,
              const int* __restrict__ farp,
              float* __restrict__ out)
{
    const int tt = threadIdx.x;
    const int p  = blockIdx.x * BP + tt;
    const int r  = p >> 6;
    const int s  = p & 63;

    // ---------- phase 0a: weight loads + stage + gather ----------
    for (int t = tt; t < 1024; t += NT) { int i = t >> 6, j = t & 63; sm[OFF_W1T + t] = w1[j*16 + i]; }
    for (int t = tt; t < 1024; t += NT) sm[OFF_W1 + t] = w1[t];
    for (int t = tt; t < 1024; t += NT) { int k = t >> 4, i = t & 15; sm[OFF_W3T + t] = w3[i*64 + k]; }
    for (int t = tt; t < 64; t += NT) {
        sm[OFF_B1 + t] = b1[t]; sm[OFF_B2 + t] = b2[t];
        sm[OFF_CB1 + t] = cb1[t]; sm[OFF_CB2 + t] = cb2[t];
    }
    if (tt < 16) sm[OFF_B3 + tt] = b3[tt];
    if (tt < 4)  sm[OFF_CB3 + tt] = (tt < 3) ? cb3[tt] : 0.0f;
    for (int t = tt; t < 256; t += NT) { int k = t >> 2, i = t & 3; sm[OFF_CW3T + t] = (i < 3) ? cw3[i*64 + k] : 0.0f; }
    // stage w2 coalesced with pitch 65 (for transpose into Wt2)
    for (int t = tt; t < 4096; t += NT) { int j = t >> 6, k = t & 63; sm[OFF_HB + j*65 + k] = w2[t]; }

    // ---- per-point setup + trilinear gather (all 8 corners, this thread) ----
    float nearf = (float)nearp[0];
    float farf  = (float)farp[0];
    float dt    = (farf - nearf) * (1.0f / (float)SAMP);
    float tmid  = nearf + ((float)s + 0.5f) * dt;

    float f[3]; int i0[3]; bool inb[3];
    #pragma unroll
    for (int c = 0; c < 3; c++) {
        float o = rays_o[3*r + c];
        float d = rays_d[3*r + c];
        float xcc = __fadd_rn(o, __fmul_rn(tmid, d));
        float graw = __fmul_rn(__fmul_rn(__fadd_rn(__fdiv_rn(xcc, 1.3f), 1.0f), 0.5f), 127.0f);
        inb[c] = (graw >= 0.0f) && (graw <= 127.0f);
        float gg = fminf(fmaxf(graw, 0.0f), 127.0f);
        int ii = (int)floorf(gg);
        if (ii > 126) ii = 126;
        i0[c] = ii;
        f[c] = gg - (float)ii;
    }
    const bool mask = inb[0] && inb[1] && inb[2];
    const int base000 = (i0[0]*GS + i0[1])*GS + i0[2];

    {
        float wx[2] = {1.0f - f[0], f[0]};
        float wy[2] = {1.0f - f[1], f[1]};
        float wz[2] = {1.0f - f[2], f[2]};
        float emb[EE];
        #pragma unroll
        for (int i = 0; i < EE; i++) emb[i] = 0.0f;
        #pragma unroll
        for (int c = 0; c < 8; c++) {
            const int dx = (c >> 2) & 1, dy = (c >> 1) & 1, dz = c & 1;
            const float w = wx[dx] * wy[dy] * wz[dz];
            const float4* cp = reinterpret_cast<const float4*>(
                grid + (size_t)(base000 + dx*(GS*GS) + dy*GS + dz) * EE);
            #pragma unroll
            for (int q = 0; q < 4; q++) {
                float4 v = cp[q];
                emb[4*q+0] = fmaf(w, v.x, emb[4*q+0]);
                emb[4*q+1] = fmaf(w, v.y, emb[4*q+1]);
                emb[4*q+2] = fmaf(w, v.z, emb[4*q+2]);
                emb[4*q+3] = fmaf(w, v.w, emb[4*q+3]);
            }
        }
        #pragma unroll
        for (int i = 0; i < EE; i++) sm[OFF_F + i*BP + tt] = emb[i];
    }
    __syncthreads();

    // ---------- phase 0b: transpose Wt2 + L1 fwd GEMM ----------
    for (int t = tt; t < 4096; t += NT) { int k = t >> 6, j = t & 63; sm[OFF_WBIG + k*64 + j] = sm[OFF_HB + j*65 + k]; }
    gemm128<16, 0>(sm + OFF_W1T, sm + OFF_F, sm + OFF_HA, sm + OFF_B1, tt);
    __syncthreads();

    // ---------- phase 2: L2 fwd GEMM ----------
    gemm128<64, 0>(sm + OFF_WBIG, sm + OFF_HA, sm + OFF_HB, sm + OFF_B2, tt);
    __syncthreads();

    // ---------- phase 3: load W2 (bwd layout) + L3 fwd (packed) + dz2 + sigma ----------
    for (int t = tt; t < 4096; t += NT) sm[OFF_WBIG + t] = w2[t];
    {
        u64 op[8];
        #pragma unroll
        for (int i = 0; i < 8; i++) op[i] = 0ull;
        #pragma unroll 8
        for (int k = 0; k < 64; k++) {
            float h2k = sm[OFF_HB + k*BP + tt];
            u64 ak = pack2(h2k, h2k);
            const ulonglong2* wr = reinterpret_cast<const ulonglong2*>(&sm[OFF_W3T + k*16]);
            ulonglong2 W0 = wr[0], W1 = wr[1];
            op[0] = fma2(ak, W0.x, op[0]);
            op[1] = fma2(ak, W0.y, op[1]);
            op[2] = fma2(ak, W1.x, op[2]);
            op[3] = fma2(ak, W1.y, op[3]);
            ulonglong2 W2v = wr[2], W3v = wr[3];
            op[4] = fma2(ak, W2v.x, op[4]);
            op[5] = fma2(ak, W2v.y, op[5]);
            op[6] = fma2(ak, W3v.x, op[6]);
            op[7] = fma2(ak, W3v.y, op[7]);
            // dz2 overwrite (same column owned by this thread)
            float dz2 = sm[OFF_W3T + k*16 + 0] * (1.0f - __expf(-100.0f * h2k));
            sm[OFF_HB + k*BP + tt] = dz2;
        }
        float o[16];
        #pragma unroll
        for (int i2 = 0; i2 < 8; i2++) {
            float2 v = unpack2(op[i2]);
            o[2*i2+0] = v.x;
            o[2*i2+1] = v.y;
        }
        float sdf = o[0] + sm[OFF_B3 + 0];
        #pragma unroll
        for (int i = 1; i < 16; i++) sm[OFF_F + (i-1)*BP + tt] = o[i] + sm[OFF_B3 + i];
        // Laplace-CDF sigma
        float be  = 0.015f + fabsf(beta[0]);
        float as  = fabsf(sdf);
        float em1 = __expf(-as / be) - 1.0f;
        float sgn = (sdf > 0.0f) ? 1.0f : ((sdf < 0.0f) ? -1.0f : 0.0f);
        float sg  = (0.5f + 0.5f * sgn * em1) / be;
        g_sigma[p] = mask ? sg : 0.0f;
    }
    __syncthreads();

    // ---------- phase 4: L2 bwd GEMM (dz1 into HA, using sigma' from h1) ----------
    gemm128<64, 2>(sm + OFF_WBIG, sm + OFF_HB, sm + OFF_HA, sm + OFF_B1, tt);
    __syncthreads();

    // ---------- phase 5: load CW1t + stage cw2 + d_emb (packed) + trilinear bwd ----------
    for (int t = tt; t < 18*64; t += NT) { int i = t >> 6, j = t & 63; sm[OFF_WBIG + t] = cw1[j*CIN + i]; }
    for (int t = tt; t < 4096; t += NT) { int j = t >> 6, k = t & 63; sm[OFF_HB + j*65 + k] = cw2[t]; }
    {
        u64 op[8];
        #pragma unroll
        for (int i = 0; i < 8; i++) op[i] = 0ull;
        #pragma unroll 8
        for (int j = 0; j < 64; j++) {
            float d = sm[OFF_HA + j*BP + tt];
            u64 ak = pack2(d, d);
            const ulonglong2* wr = reinterpret_cast<const ulonglong2*>(&sm[OFF_W1 + j*16]);
            ulonglong2 W0 = wr[0], W1 = wr[1];
            op[0] = fma2(ak, W0.x, op[0]);
            op[1] = fma2(ak, W0.y, op[1]);
            op[2] = fma2(ak, W1.x, op[2]);
            op[3] = fma2(ak, W1.y, op[3]);
            ulonglong2 W2v = wr[2], W3v = wr[3];
            op[4] = fma2(ak, W2v.x, op[4]);
            op[5] = fma2(ak, W2v.y, op[5]);
            op[6] = fma2(ak, W3v.x, op[6]);
            op[7] = fma2(ak, W3v.y, op[7]);
        }
        float o[16];
        #pragma unroll
        for (int i2 = 0; i2 < 8; i2++) {
            float2 v = unpack2(op[i2]);
            o[2*i2+0] = v.x;
            o[2*i2+1] = v.y;
        }
        // trilinear backward: re-gather corners, dot with o (=d_emb)
        float wx[2] = {1.0f - f[0], f[0]};
        float wy[2] = {1.0f - f[1], f[1]};
        float wz[2] = {1.0f - f[2], f[2]};
        float gx = 0.0f, gy = 0.0f, gz = 0.0f;
        #pragma unroll
        for (int c = 0; c < 8; c++) {
            const int dx = (c >> 2) & 1, dy = (c >> 1) & 1, dz = c & 1;
            const float4* cp = reinterpret_cast<const float4*>(
                grid + (size_t)(base000 + dx*(GS*GS) + dy*GS + dz) * EE);
            float dot = 0.0f;
            #pragma unroll
            for (int q = 0; q < 4; q++) {
                float4 v = cp[q];
                dot = fmaf(o[4*q+0], v.x, dot);
                dot = fmaf(o[4*q+1], v.y, dot);
                dot = fmaf(o[4*q+2], v.z, dot);
                dot = fmaf(o[4*q+3], v.w, dot);
            }
            float sx = dx ? 1.0f : -1.0f;
            float sy = dy ? 1.0f : -1.0f;
            float sz = dz ? 1.0f : -1.0f;
            gx = fmaf(sx * wy[dy] * wz[dz], dot, gx);
            gy = fmaf(wx[dx] * sy * wz[dz], dot, gy);
            gz = fmaf(wx[dx] * wy[dy] * sz, dot, gz);
        }
        const float K = 48.846153846153847f;   // 0.5*(G-1)/BOUND
        float dX = gx * (inb[0] ? K : 0.0f);
        float dY = gy * (inb[1] ? K : 0.0f);
        float dZ = gz * (inb[2] ? K : 0.0f);
        out[RAYS*8 + 3*p + 0] = dX;
        out[RAYS*8 + 3*p + 1] = dY;
        out[RAYS*8 + 3*p + 2] = dZ;
        float nn  = fmaxf(sqrtf(dX*dX + dY*dY + dZ*dZ), 1e-12f);
        float inv = 1.0f / nn;
        sm[OFF_F + 15*BP + tt] = dX * inv;
        sm[OFF_F + 16*BP + tt] = dY * inv;
        sm[OFF_F + 17*BP + tt] = dZ * inv;
    }
    __syncthreads();

    // ---------- phase 6: color L1 GEMM ----------
    gemm128<18, 1>(sm + OFF_WBIG, sm + OFF_F, sm + OFF_HA, sm + OFF_CB1, tt);
    __syncthreads();

    // ---------- phase 7: transpose CWt2 ----------
    for (int t = tt; t < 4096; t += NT) { int k = t >> 6, j = t & 63; sm[OFF_WBIG + k*64 + j] = sm[OFF_HB + j*65 + k]; }
    __syncthreads();

    // ---------- phase 8: color L2 GEMM ----------
    gemm128<64, 1>(sm + OFF_WBIG, sm + OFF_HA, sm + OFF_HB, sm + OFF_CB2, tt);
    __syncthreads();

    // ---------- phase 9: color L3 (scalar) ----------
    {
        float a0 = 0.0f, a1 = 0.0f, a2 = 0.0f;
        #pragma unroll 8
        for (int k = 0; k < 64; k++) {
            float hk = sm[OFF_HB + k*BP + tt];
            float4 cw = *(const float4*)&sm[OFF_CW3T + k*4];
            a0 = fmaf(hk, cw.x, a0);
            a1 = fmaf(hk, cw.y, a1);
            a2 = fmaf(hk, cw.z, a2);
        }
        a0 += sm[OFF_CB3 + 0];
        a1 += sm[OFF_CB3 + 1];
        a2 += sm[OFF_CB3 + 2];
        g_rgb[3*p + 0] = 1.0f / (1.0f + __expf(-a0));
        g_rgb[3*p + 1] = 1.0f / (1.0f + __expf(-a1));
        g_rgb[3*p + 2] = 1.0f / (1.0f + __expf(-a2));
    }
}

__global__ void __launch_bounds__(128)
render_kernel(const float* __restrict__ rays_d_norm,
              const int* __restrict__ nearp, const int* __restrict__ farp,
              float* __restrict__ out)
{
    int r = blockIdx.x * 128 + threadIdx.x;
    if (r >= RAYS) return;
    float nearf = (float)nearp[0];
    float farf  = (float)farp[0];
    float dt    = (farf - nearf) * (1.0f / (float)SAMP);
    const float* grads = out + RAYS*8;

    float cs = 0.0f;
    float aR = 0.f, aG = 0.f, aB = 0.f, aD = 0.f;
    float aN0 = 0.f, aN1 = 0.f, aN2 = 0.f, aA = 0.f;
    for (int s = 0; s < SAMP; s++) {
        int p = r * SAMP + s;
        float dd = g_sigma[p] * dt;
        float T  = __expf(-cs);          // exclusive prefix
        cs += dd;
        float w = (1.0f - __expf(-dd)) * T;
        aR = fmaf(w, g_rgb[3*p + 0], aR);
        aG = fmaf(w, g_rgb[3*p + 1], aG);
        aB = fmaf(w, g_rgb[3*p + 2], aB);
        float tm = nearf + ((float)s + 0.5f) * dt;
        aD = fmaf(w, tm, aD);
        float gx = grads[3*p + 0], gy = grads[3*p + 1], gz = grads[3*p + 2];
        float nn = fmaxf(sqrtf(gx*gx + gy*gy + gz*gz), 1e-12f);
        float wi = w / nn;
        aN0 = fmaf(wi, gx, aN0);
        aN1 = fmaf(wi, gy, aN1);
        aN2 = fmaf(wi, gz, aN2);
        aA += w;
    }
    float ir = 1.0f / rays_d_norm[r];
    out[8*r + 0] = aR;
    out[8*r + 1] = aG;
    out[8*r + 2] = aB;
    out[8*r + 3] = aD * ir;
    out[8*r + 4] = aN0;
    out[8*r + 5] = aN1;
    out[8*r + 6] = aN2;
    out[8*r + 7] = aA;
}

extern "C" void kernel_launch(void* const* d_in, const int* in_sizes, int n_in,
                              void* d_out, int out_size)
{
    const float* rays_o      = (const float*)d_in[0];
    const float* rays_d      = (const float*)d_in[1];
    const float* rays_d_norm = (const float*)d_in[2];
    const float* grid        = (const float*)d_in[3];
    const float* sw1 = (const float*)d_in[4];
    const float* sb1 = (const float*)d_in[5];
    const float* sw2 = (const float*)d_in[6];
    const float* sb2 = (const float*)d_in[7];
    const float* sw3 = (const float*)d_in[8];
    const float* sb3 = (const float*)d_in[9];
    const float* cw1 = (const float*)d_in[10];
    const float* cb1 = (const float*)d_in[11];
    const float* cw2 = (const float*)d_in[12];
    const float* cb2 = (const float*)d_in[13];
    const float* cw3 = (const float*)d_in[14];
    const float* cb3 = (const float*)d_in[15];
    const float* beta  = (const float*)d_in[16];
    const int*   nearp = (const int*)d_in[17];
    const int*   farp  = (const int*)d_in[18];
    float* out = (float*)d_out;

    cudaFuncSetAttribute(points_kernel,
                         cudaFuncAttributeMaxDynamicSharedMemorySize, SM_BYTES);

    points_kernel<<<NP/BP, NT, SM_BYTES>>>(rays_o, rays_d, grid,
                                           sw1, sb1, sw2, sb2, sw3, sb3,
                                           cw1, cb1, cw2, cb2, cw3, cb3,
                                           beta, nearp, farp, out);
    render_kernel<<<RAYS/128, 128>>>(rays_d_norm, nearp, farp, out);
}

// round 8
// speedup vs baseline: 6.0340x; 1.0671x over previous
#include <cuda_runtime.h>

#define RAYS 16384
#define SAMP 64
#define NP (RAYS*SAMP)
#define GS 128
#define EE 16
#define HH 64
#define CIN 18
#define BP 128            // points per block
#define NT 128            // threads per block

// Scratch (device globals; no allocation allowed)
__device__ float g_rgb[NP*3];
__device__ float g_sigma[NP];

// ---- dynamic smem float offsets (all float4-aligned where needed) ----
#define OFF_W1T   0        // [16][64]  W1t[i][j] = w1[j*16+i]
#define OFF_W1    1024     // [64][16]  w1 row-major
#define OFF_W3T   2048     // [64][16]  W3t[k][i] = w3[i*64+k]
#define OFF_B1    3072     // 64
#define OFF_B2    3136     // 64
#define OFF_B3    3200     // 16
#define OFF_CB1   3216     // 64
#define OFF_CB2   3280     // 64
#define OFF_CB3   3344     // 4
#define OFF_CW3T  3348     // [64][4]   CW3t[k][i] = cw3[i*64+k]
#define OFF_WBIG  3604     // [64][64]  Wt2 -> W2 -> CW1t -> CWt2
#define OFF_F     7700     // [18][128] emb/feat+normals
#define OFF_HA    10004    // [64][128]
#define OFF_HB    18196    // [64][128] (also 64x65 stage area)
#define SM_FLOATS 26388
#define SM_BYTES  (SM_FLOATS*4)

extern __shared__ float sm[];

typedef unsigned long long u64;

__device__ __forceinline__ u64 pack2(float x, float y) {
    u64 d;
    asm("mov.b64 %0, {%1, %2};" : "=l"(d) : "f"(x), "f"(y));
    return d;
}
__device__ __forceinline__ u64 fma2(u64 a, u64 b, u64 c) {
    u64 d;
    asm("fma.rn.f32x2 %0, %1, %2, %3;" : "=l"(d) : "l"(a), "l"(b), "l"(c));
    return d;
}
__device__ __forceinline__ float2 unpack2(u64 v) {
    float2 r;
    asm("mov.b64 {%0, %1}, %2;" : "=f"(r.x), "=f"(r.y) : "l"(v));
    return r;
}

__device__ __forceinline__ float softplus100(float z) {
    float a = 100.0f * z;
    float sp = fmaxf(a, 0.0f) + __logf(1.0f + __expf(-fabsf(a)));
    return 0.01f * sp;
}

// Tile: 4 points x 16 units per thread. Warp shares one unit group ->
// weight LDS are warp-broadcast and consumed directly as packed (w_{2j},w_{2j+1})
// pairs (no weight-pack MOVs); only 4 A-duplication MOVs per k.
// MODE 0: softplus100(acc + bias); MODE 1: relu(acc + bias);
// MODE 2: dz1 = acc * (1 - exp(-100 * h_prev)) with h_prev read from Hout.
template<int K, int MODE>
__device__ __forceinline__ void gemm128(const float* __restrict__ Wt,
                                        const float* __restrict__ Hin,
                                        float* __restrict__ Hout,
                                        const float* __restrict__ bias,
                                        int tt)
{
    const int pt0 = (tt & 31) * 4;
    const int u0  = (tt >> 5) * 16;
    u64 acc[4][8];
    #pragma unroll
    for (int i = 0; i < 4; i++)
        #pragma unroll
        for (int j = 0; j < 8; j++) acc[i][j] = 0ull;

    #pragma unroll 8
    for (int k = 0; k < K; k++) {
        float4 av = *(const float4*)&Hin[k*BP + pt0];
        u64 a[4] = {pack2(av.x, av.x), pack2(av.y, av.y),
                    pack2(av.z, av.z), pack2(av.w, av.w)};
        const ulonglong2* wp = (const ulonglong2*)&Wt[k*64 + u0];
        ulonglong2 W01 = wp[0], W23 = wp[1], W45 = wp[2], W67 = wp[3];
        u64 w[8] = {W01.x, W01.y, W23.x, W23.y, W45.x, W45.y, W67.x, W67.y};
        #pragma unroll
        for (int i = 0; i < 4; i++)
            #pragma unroll
            for (int j = 0; j < 8; j++)
                acc[i][j] = fma2(a[i], w[j], acc[i][j]);
    }

    float4 bi[4];
    if (MODE != 2) {
        #pragma unroll
        for (int q = 0; q < 4; q++) bi[q] = *(const float4*)&bias[u0 + 4*q];
    }
    const float* bs = (const float*)bi;

    #pragma unroll
    for (int j = 0; j < 8; j++) {
        float2 r0 = unpack2(acc[0][j]);
        float2 r1 = unpack2(acc[1][j]);
        float2 r2 = unpack2(acc[2][j]);
        float2 r3 = unpack2(acc[3][j]);
        #pragma unroll
        for (int b = 0; b < 2; b++) {
            const int u = u0 + 2*j + b;
            float z0 = b ? r0.y : r0.x;
            float z1 = b ? r1.y : r1.x;
            float z2 = b ? r2.y : r2.x;
            float z3 = b ? r3.y : r3.x;
            float* orow = &Hout[u*BP + pt0];
            float res0, res1, res2, res3;
            if (MODE == 2) {
                float4 vin = *(const float4*)orow;
                res0 = z0 * (1.0f - __expf(-100.0f * vin.x));
                res1 = z1 * (1.0f - __expf(-100.0f * vin.y));
                res2 = z2 * (1.0f - __expf(-100.0f * vin.z));
                res3 = z3 * (1.0f - __expf(-100.0f * vin.w));
            } else {
                float bj = bs[2*j + b];
                if (MODE == 0) {
                    res0 = softplus100(z0 + bj);
                    res1 = softplus100(z1 + bj);
                    res2 = softplus100(z2 + bj);
                    res3 = softplus100(z3 + bj);
                } else {
                    res0 = fmaxf(z0 + bj, 0.0f);
                    res1 = fmaxf(z1 + bj, 0.0f);
                    res2 = fmaxf(z2 + bj, 0.0f);
                    res3 = fmaxf(z3 + bj, 0.0f);
                }
            }
            *(float4*)orow = make_float4(res0, res1, res2, res3);
        }
    }
}

__global__ void __launch_bounds__(NT)
points_kernel(const float* __restrict__ rays_o,
              const float* __restrict__ rays_d,
              const float* __restrict__ grid,
              const float* __restrict__ w1, const float* __restrict__ b1,
              const float* __restrict__ w2, const float* __restrict__ b2,
              const float* __restrict__ w3, const float* __restrict__ b3,
              const float* __restrict__ cw1, const float* __restrict__ cb1,
              const float* __restrict__ cw2, const float* __restrict__ cb2,
              const float* __restrict__ cw3, const float* __restrict__ cb3,
              const float* __restrict__ beta,
              const int* __restrict__ nearp,
              const int* __restrict__ farp,
              float* __restrict__ out)
{
    const int tt = threadIdx.x;
    const int p  = blockIdx.x * BP + tt;
    const int r  = p >> 6;
    const int s  = p & 63;

    // ---------- phase 0a: weight loads + stage + gather ----------
    for (int t = tt; t < 1024; t += NT) { int i = t >> 6, j = t & 63; sm[OFF_W1T + t] = w1[j*16 + i]; }
    for (int t = tt; t < 1024; t += NT) sm[OFF_W1 + t] = w1[t];
    for (int t = tt; t < 1024; t += NT) { int k = t >> 4, i = t & 15; sm[OFF_W3T + t] = w3[i*64 + k]; }
    for (int t = tt; t < 64; t += NT) {
        sm[OFF_B1 + t] = b1[t]; sm[OFF_B2 + t] = b2[t];
        sm[OFF_CB1 + t] = cb1[t]; sm[OFF_CB2 + t] = cb2[t];
    }
    if (tt < 16) sm[OFF_B3 + tt] = b3[tt];
    if (tt < 4)  sm[OFF_CB3 + tt] = (tt < 3) ? cb3[tt] : 0.0f;
    for (int t = tt; t < 256; t += NT) { int k = t >> 2, i = t & 3; sm[OFF_CW3T + t] = (i < 3) ? cw3[i*64 + k] : 0.0f; }
    // stage w2 coalesced with pitch 65 (for transpose into Wt2)
    for (int t = tt; t < 4096; t += NT) { int j = t >> 6, k = t & 63; sm[OFF_HB + j*65 + k] = w2[t]; }

    // ---- per-point setup + trilinear gather (all 8 corners, this thread) ----
    float nearf = (float)nearp[0];
    float farf  = (float)farp[0];
    float dt    = (farf - nearf) * (1.0f / (float)SAMP);
    float tmid  = nearf + ((float)s + 0.5f) * dt;

    float f[3]; int i0[3]; bool inb[3];
    #pragma unroll
    for (int c = 0; c < 3; c++) {
        float o = rays_o[3*r + c];
        float d = rays_d[3*r + c];
        float xcc = __fadd_rn(o, __fmul_rn(tmid, d));
        float graw = __fmul_rn(__fmul_rn(__fadd_rn(__fdiv_rn(xcc, 1.3f), 1.0f), 0.5f), 127.0f);
        inb[c] = (graw >= 0.0f) && (graw <= 127.0f);
        float gg = fminf(fmaxf(graw, 0.0f), 127.0f);
        int ii = (int)floorf(gg);
        if (ii > 126) ii = 126;
        i0[c] = ii;
        f[c] = gg - (float)ii;
    }
    const bool mask = inb[0] && inb[1] && inb[2];
    const int base000 = (i0[0]*GS + i0[1])*GS + i0[2];

    {
        float wx[2] = {1.0f - f[0], f[0]};
        float wy[2] = {1.0f - f[1], f[1]};
        float wz[2] = {1.0f - f[2], f[2]};
        float emb[EE];
        #pragma unroll
        for (int i = 0; i < EE; i++) emb[i] = 0.0f;
        #pragma unroll
        for (int c = 0; c < 8; c++) {
            const int dx = (c >> 2) & 1, dy = (c >> 1) & 1, dz = c & 1;
            const float w = wx[dx] * wy[dy] * wz[dz];
            const float4* cp = reinterpret_cast<const float4*>(
                grid + (size_t)(base000 + dx*(GS*GS) + dy*GS + dz) * EE);
            #pragma unroll
            for (int q = 0; q < 4; q++) {
                float4 v = cp[q];
                emb[4*q+0] = fmaf(w, v.x, emb[4*q+0]);
                emb[4*q+1] = fmaf(w, v.y, emb[4*q+1]);
                emb[4*q+2] = fmaf(w, v.z, emb[4*q+2]);
                emb[4*q+3] = fmaf(w, v.w, emb[4*q+3]);
            }
        }
        #pragma unroll
        for (int i = 0; i < EE; i++) sm[OFF_F + i*BP + tt] = emb[i];
    }
    __syncthreads();

    // ---------- phase 0b: transpose Wt2 + L1 fwd GEMM ----------
    for (int t = tt; t < 4096; t += NT) { int k = t >> 6, j = t & 63; sm[OFF_WBIG + k*64 + j] = sm[OFF_HB + j*65 + k]; }
    gemm128<16, 0>(sm + OFF_W1T, sm + OFF_F, sm + OFF_HA, sm + OFF_B1, tt);
    __syncthreads();

    // ---------- phase 2: L2 fwd GEMM ----------
    gemm128<64, 0>(sm + OFF_WBIG, sm + OFF_HA, sm + OFF_HB, sm + OFF_B2, tt);
    __syncthreads();

    // ---------- phase 3: load W2 (bwd layout) + L3 fwd (packed) + dz2 + sigma ----------
    for (int t = tt; t < 4096; t += NT) sm[OFF_WBIG + t] = w2[t];
    {
        u64 op[8];
        #pragma unroll
        for (int i = 0; i < 8; i++) op[i] = 0ull;
        #pragma unroll 8
        for (int k = 0; k < 64; k++) {
            float h2k = sm[OFF_HB + k*BP + tt];
            u64 ak = pack2(h2k, h2k);
            const ulonglong2* wr = reinterpret_cast<const ulonglong2*>(&sm[OFF_W3T + k*16]);
            ulonglong2 W0 = wr[0], W1 = wr[1];
            op[0] = fma2(ak, W0.x, op[0]);
            op[1] = fma2(ak, W0.y, op[1]);
            op[2] = fma2(ak, W1.x, op[2]);
            op[3] = fma2(ak, W1.y, op[3]);
            ulonglong2 W2v = wr[2], W3v = wr[3];
            op[4] = fma2(ak, W2v.x, op[4]);
            op[5] = fma2(ak, W2v.y, op[5]);
            op[6] = fma2(ak, W3v.x, op[6]);
            op[7] = fma2(ak, W3v.y, op[7]);
            // dz2 overwrite (same column owned by this thread)
            float dz2 = sm[OFF_W3T + k*16 + 0] * (1.0f - __expf(-100.0f * h2k));
            sm[OFF_HB + k*BP + tt] = dz2;
        }
        float o[16];
        #pragma unroll
        for (int i2 = 0; i2 < 8; i2++) {
            float2 v = unpack2(op[i2]);
            o[2*i2+0] = v.x;
            o[2*i2+1] = v.y;
        }
        float sdf = o[0] + sm[OFF_B3 + 0];
        #pragma unroll
        for (int i = 1; i < 16; i++) sm[OFF_F + (i-1)*BP + tt] = o[i] + sm[OFF_B3 + i];
        // Laplace-CDF sigma
        float be  = 0.015f + fabsf(beta[0]);
        float as  = fabsf(sdf);
        float em1 = __expf(-as / be) - 1.0f;
        float sgn = (sdf > 0.0f) ? 1.0f : ((sdf < 0.0f) ? -1.0f : 0.0f);
        float sg  = (0.5f + 0.5f * sgn * em1) / be;
        g_sigma[p] = mask ? sg : 0.0f;
    }
    __syncthreads();

    // ---------- phase 4: L2 bwd GEMM (dz1 into HA, using sigma' from h1) ----------
    gemm128<64, 2>(sm + OFF_WBIG, sm + OFF_HB, sm + OFF_HA, sm + OFF_B1, tt);
    __syncthreads();

    // ---------- phase 5: load CW1t + stage cw2 + d_emb (packed) + trilinear bwd ----------
    for (int t = tt; t < 18*64; t += NT) { int i = t >> 6, j = t & 63; sm[OFF_WBIG + t] = cw1[j*CIN + i]; }
    for (int t = tt; t < 4096; t += NT) { int j = t >> 6, k = t & 63; sm[OFF_HB + j*65 + k] = cw2[t]; }
    {
        u64 op[8];
        #pragma unroll
        for (int i = 0; i < 8; i++) op[i] = 0ull;
        #pragma unroll 8
        for (int j = 0; j < 64; j++) {
            float d = sm[OFF_HA + j*BP + tt];
            u64 ak = pack2(d, d);
            const ulonglong2* wr = reinterpret_cast<const ulonglong2*>(&sm[OFF_W1 + j*16]);
            ulonglong2 W0 = wr[0], W1 = wr[1];
            op[0] = fma2(ak, W0.x, op[0]);
            op[1] = fma2(ak, W0.y, op[1]);
            op[2] = fma2(ak, W1.x, op[2]);
            op[3] = fma2(ak, W1.y, op[3]);
            ulonglong2 W2v = wr[2], W3v = wr[3];
            op[4] = fma2(ak, W2v.x, op[4]);
            op[5] = fma2(ak, W2v.y, op[5]);
            op[6] = fma2(ak, W3v.x, op[6]);
            op[7] = fma2(ak, W3v.y, op[7]);
        }
        float o[16];
        #pragma unroll
        for (int i2 = 0; i2 < 8; i2++) {
            float2 v = unpack2(op[i2]);
            o[2*i2+0] = v.x;
            o[2*i2+1] = v.y;
        }
        // trilinear backward: re-gather corners, dot with o (=d_emb)
        float wx[2] = {1.0f - f[0], f[0]};
        float wy[2] = {1.0f - f[1], f[1]};
        float wz[2] = {1.0f - f[2], f[2]};
        float gx = 0.0f, gy = 0.0f, gz = 0.0f;
        #pragma unroll
        for (int c = 0; c < 8; c++) {
            const int dx = (c >> 2) & 1, dy = (c >> 1) & 1, dz = c & 1;
            const float4* cp = reinterpret_cast<const float4*>(
                grid + (size_t)(base000 + dx*(GS*GS) + dy*GS + dz) * EE);
            float dot = 0.0f;
            #pragma unroll
            for (int q = 0; q < 4; q++) {
                float4 v = cp[q];
                dot = fmaf(o[4*q+0], v.x, dot);
                dot = fmaf(o[4*q+1], v.y, dot);
                dot = fmaf(o[4*q+2], v.z, dot);
                dot = fmaf(o[4*q+3], v.w, dot);
            }
            float sx = dx ? 1.0f : -1.0f;
            float sy = dy ? 1.0f : -1.0f;
            float sz = dz ? 1.0f : -1.0f;
            gx = fmaf(sx * wy[dy] * wz[dz], dot, gx);
            gy = fmaf(wx[dx] * sy * wz[dz], dot, gy);
            gz = fmaf(wx[dx] * wy[dy] * sz, dot, gz);
        }
        const float K = 48.846153846153847f;   // 0.5*(G-1)/BOUND
        float dX = gx * (inb[0] ? K : 0.0f);
        float dY = gy * (inb[1] ? K : 0.0f);
        float dZ = gz * (inb[2] ? K : 0.0f);
        out[RAYS*8 + 3*p + 0] = dX;
        out[RAYS*8 + 3*p + 1] = dY;
        out[RAYS*8 + 3*p + 2] = dZ;
        float nn  = fmaxf(sqrtf(dX*dX + dY*dY + dZ*dZ), 1e-12f);
        float inv = 1.0f / nn;
        sm[OFF_F + 15*BP + tt] = dX * inv;
        sm[OFF_F + 16*BP + tt] = dY * inv;
        sm[OFF_F + 17*BP + tt] = dZ * inv;
    }
    __syncthreads();

    // ---------- phase 6: color L1 GEMM ----------
    gemm128<18, 1>(sm + OFF_WBIG, sm + OFF_F, sm + OFF_HA, sm + OFF_CB1, tt);
    __syncthreads();

    // ---------- phase 7: transpose CWt2 ----------
    for (int t = tt; t < 4096; t += NT) { int k = t >> 6, j = t & 63; sm[OFF_WBIG + k*64 + j] = sm[OFF_HB + j*65 + k]; }
    __syncthreads();

    // ---------- phase 8: color L2 GEMM ----------
    gemm128<64, 1>(sm + OFF_WBIG, sm + OFF_HA, sm + OFF_HB, sm + OFF_CB2, tt);
    __syncthreads();

    // ---------- phase 9: color L3 (scalar) ----------
    {
        float a0 = 0.0f, a1 = 0.0f, a2 = 0.0f;
        #pragma unroll 8
        for (int k = 0; k < 64; k++) {
            float hk = sm[OFF_HB + k*BP + tt];
            float4 cw = *(const float4*)&sm[OFF_CW3T + k*4];
            a0 = fmaf(hk, cw.x, a0);
            a1 = fmaf(hk, cw.y, a1);
            a2 = fmaf(hk, cw.z, a2);
        }
        a0 += sm[OFF_CB3 + 0];
        a1 += sm[OFF_CB3 + 1];
        a2 += sm[OFF_CB3 + 2];
        g_rgb[3*p + 0] = 1.0f / (1.0f + __expf(-a0));
        g_rgb[3*p + 1] = 1.0f / (1.0f + __expf(-a1));
        g_rgb[3*p + 2] = 1.0f / (1.0f + __expf(-a2));
    }
}

// ---------------- render: 1 block (64 threads) per ray, shfl scan ----------------
__global__ void __launch_bounds__(64)
render_kernel(const float* __restrict__ rays_d_norm,
              const int* __restrict__ nearp, const int* __restrict__ farp,
              float* __restrict__ out)
{
    __shared__ float red[64*8];
    __shared__ float warp0_total;
    const int r = blockIdx.x;
    const int s = threadIdx.x;
    const int lane = s & 31;
    const int wrp  = s >> 5;
    const int p = r * SAMP + s;

    float nearf = (float)nearp[0];
    float farf  = (float)farp[0];
    float dt    = (farf - nearf) * (1.0f / (float)SAMP);
    const float* grads = out + RAYS*8;

    float dd = g_sigma[p] * dt;

    // inclusive scan of dd across 64 threads
    float cs = dd;
    #pragma unroll
    for (int o = 1; o < 32; o <<= 1) {
        float v = __shfl_up_sync(0xffffffffu, cs, o);
        if (lane >= o) cs += v;
    }
    if (wrp == 0 && lane == 31) warp0_total = cs;
    __syncthreads();
    if (wrp == 1) cs += warp0_total;

    float T = __expf(-(cs - dd));
    float w = (1.0f - __expf(-dd)) * T;

    float rgb0 = g_rgb[3*p + 0], rgb1 = g_rgb[3*p + 1], rgb2 = g_rgb[3*p + 2];
    float gx = grads[3*p + 0], gy = grads[3*p + 1], gz = grads[3*p + 2];
    float nn = fmaxf(sqrtf(gx*gx + gy*gy + gz*gz), 1e-12f);
    float wi = w / nn;
    float tm = nearf + ((float)s + 0.5f) * dt;

    red[s*8 + 0] = w * rgb0;
    red[s*8 + 1] = w * rgb1;
    red[s*8 + 2] = w * rgb2;
    red[s*8 + 3] = w * tm;
    red[s*8 + 4] = wi * gx;
    red[s*8 + 5] = wi * gy;
    red[s*8 + 6] = wi * gz;
    red[s*8 + 7] = w;
    __syncthreads();

    // tree reduce 64 rows of 8 floats
    #pragma unroll
    for (int stride = 32; stride >= 1; stride >>= 1) {
        if (s < stride) {
            float4 a0 = *(float4*)&red[s*8];
            float4 a1 = *(float4*)&red[s*8 + 4];
            float4 b0 = *(float4*)&red[(s+stride)*8];
            float4 b1 = *(float4*)&red[(s+stride)*8 + 4];
            a0.x += b0.x; a0.y += b0.y; a0.z += b0.z; a0.w += b0.w;
            a1.x += b1.x; a1.y += b1.y; a1.z += b1.z; a1.w += b1.w;
            *(float4*)&red[s*8] = a0;
            *(float4*)&red[s*8 + 4] = a1;
        }
        __syncthreads();
    }

    if (s == 0) {
        float ir = 1.0f / rays_d_norm[r];
        out[8*r + 0] = red[0];
        out[8*r + 1] = red[1];
        out[8*r + 2] = red[2];
        out[8*r + 3] = red[3] * ir;
        out[8*r + 4] = red[4];
        out[8*r + 5] = red[5];
        out[8*r + 6] = red[6];
        out[8*r + 7] = red[7];
    }
}

extern "C" void kernel_launch(void* const* d_in, const int* in_sizes, int n_in,
                              void* d_out, int out_size)
{
    const float* rays_o      = (const float*)d_in[0];
    const float* rays_d      = (const float*)d_in[1];
    const float* rays_d_norm = (const float*)d_in[2];
    const float* grid        = (const float*)d_in[3];
    const float* sw1 = (const float*)d_in[4];
    const float* sb1 = (const float*)d_in[5];
    const float* sw2 = (const float*)d_in[6];
    const float* sb2 = (const float*)d_in[7];
    const float* sw3 = (const float*)d_in[8];
    const float* sb3 = (const float*)d_in[9];
    const float* cw1 = (const float*)d_in[10];
    const float* cb1 = (const float*)d_in[11];
    const float* cw2 = (const float*)d_in[12];
    const float* cb2 = (const float*)d_in[13];
    const float* cw3 = (const float*)d_in[14];
    const float* cb3 = (const float*)d_in[15];
    const float* beta  = (const float*)d_in[16];
    const int*   nearp = (const int*)d_in[17];
    const int*   farp  = (const int*)d_in[18];
    float* out = (float*)d_out;

    cudaFuncSetAttribute(points_kernel,
                         cudaFuncAttributeMaxDynamicSharedMemorySize, SM_BYTES);

    points_kernel<<<NP/BP, NT, SM_BYTES>>>(rays_o, rays_d, grid,
                                           sw1, sb1, sw2, sb2, sw3, sb3,
                                           cw1, cb1, cw2, cb2, cw3, cb3,
                                           beta, nearp, farp, out);
    render_kernel<<<RAYS, 64>>>(rays_d_norm, nearp, farp, out);
}